// round 13
// baseline (speedup 1.0000x reference)
#include <cuda_runtime.h>
#include <math.h>
#include <float.h>

#define NN 100000
#define EE 1600000
#define FH 64
#define FO 40
#define CAP 96   // padded-ELL row capacity; deg ~ Binom(1.6e6,1e-5), mean 16, sd 4

// ---------------- static scratch (no allocations allowed) ----------------
__device__ int   g_cnt[NN];
__device__ int   g_ell[(size_t)NN * CAP];
__device__ float g_agg[(size_t)NN * FH];
__device__ float g_h1[(size_t)NN * FH];
__device__ float g_h2[(size_t)NN * FH];

// ---------------- preprocessing: zero counters, then one-pass ELL build ----------
__global__ void k_zero_cnt() {
    int i = blockIdx.x * blockDim.x + threadIdx.x;
    if (i < NN) g_cnt[i] = 0;
}

__global__ void k_fill_ell(const int* __restrict__ er, const int* __restrict__ ec) {
    int e = blockIdx.x * blockDim.x + threadIdx.x;
    if (e >= EE) return;
    int r = er[e];
    int slot = atomicAdd(&g_cnt[r], 1);
    if (slot < CAP) g_ell[(size_t)r * CAP + slot] = ec[e];
}

// ---------------- aggregation: warp per node, mean over ELL neighbors ----------
__global__ __launch_bounds__(256) void k_agg(const float* __restrict__ act,
                                             float* __restrict__ agg) {
    int w    = (blockIdx.x * blockDim.x + threadIdx.x) >> 5;
    int lane = threadIdx.x & 31;
    if (w >= NN) return;
    int deg = g_cnt[w];
    int e = deg < CAP ? deg : CAP;
    const int* idx = g_ell + (size_t)w * CAP;
    float ax = 0.f, ay = 0.f, bx = 0.f, by = 0.f;
    int i = 0;
    for (; i + 1 < e; i += 2) {
        int j0 = idx[i], j1 = idx[i + 1];
        float2 v0 = *(const float2*)(act + (size_t)j0 * FH + lane * 2);
        float2 v1 = *(const float2*)(act + (size_t)j1 * FH + lane * 2);
        ax += v0.x; ay += v0.y;
        bx += v1.x; by += v1.y;
    }
    if (i < e) {
        int j0 = idx[i];
        float2 v0 = *(const float2*)(act + (size_t)j0 * FH + lane * 2);
        ax += v0.x; ay += v0.y;
    }
    float d = (deg > 0) ? (1.0f / (float)deg) : 0.0f;
    float2 r;
    r.x = (ax + bx) * d;
    r.y = (ay + by) * d;
    *(float2*)(agg + (size_t)w * FH + lane * 2) = r;
}

// ---------------- GEMM: out = A1@W1 + A2@W2 + (b1+b2)  [R2 core, occ-forced] ----
// __launch_bounds__(256, 4): cap regs at 64 so 4 blocks (32 warps) fit per SM.
// smem: sW 16KB + sA 32KB = 48KB; 4 x 48 = 192KB <= 228KB per SM.
// doFinal=1: fused log-softmax over Fo=40 outputs (16-lane shuffle reduction).
__global__ __launch_bounds__(256, 4) void k_gemm(const float* __restrict__ A1,
                                                 const float* __restrict__ A2,
                                                 const float* __restrict__ W1,
                                                 const float* __restrict__ b1,
                                                 const float* __restrict__ W2,
                                                 const float* __restrict__ b2,
                                                 float* __restrict__ out,
                                                 int Fo, int doRelu, int doFinal) {
    __shared__ float sW[64][64];
    __shared__ float sA[128][64];

    int tid = threadIdx.x;
    int tx = tid & 15;   // col group: cols tx*4 .. tx*4+3
    int ty = tid >> 4;   // row group: rows ty*8 .. ty*8+7
    int row0 = blockIdx.x * 128;

    float acc[8][4];
#pragma unroll
    for (int i = 0; i < 8; i++)
#pragma unroll
        for (int j = 0; j < 4; j++) acc[i][j] = 0.f;

    for (int pass = 0; pass < 2; ++pass) {
        const float* A = pass ? A2 : A1;
        const float* W = pass ? W2 : W1;
        if (pass) __syncthreads();  // protect smem from previous pass
        // load W (64 x Fo) into sW, zero-padded to 64 cols
        for (int i = tid; i < 64 * 16; i += 256) {
            int r = i >> 4, c4 = (i & 15) * 4;
            float4 v = {0.f, 0.f, 0.f, 0.f};
            if (c4 + 3 < Fo) v = *(const float4*)(W + (size_t)r * Fo + c4);
            *(float4*)&sW[r][c4] = v;
        }
        // load A tile (128 x 64)
        for (int i = tid; i < 128 * 16; i += 256) {
            int r = i >> 4, c4 = (i & 15) * 4;
            int gr = row0 + r;
            float4 v = {0.f, 0.f, 0.f, 0.f};
            if (gr < NN) v = *(const float4*)(A + (size_t)gr * FH + c4);
            *(float4*)&sA[r][c4] = v;
        }
        __syncthreads();
#pragma unroll 4
        for (int k = 0; k < 64; ++k) {
            float4 w = *(const float4*)&sW[k][tx * 4];
#pragma unroll
            for (int i = 0; i < 8; ++i) {
                float a = sA[ty * 8 + i][k];
                acc[i][0] = fmaf(a, w.x, acc[i][0]);
                acc[i][1] = fmaf(a, w.y, acc[i][1]);
                acc[i][2] = fmaf(a, w.z, acc[i][2]);
                acc[i][3] = fmaf(a, w.w, acc[i][3]);
            }
        }
    }

    // bias (neutral for c >= Fo lanes; they don't store)
    int c = tx * 4;
    float bb0 = 0.f, bb1 = 0.f, bb2 = 0.f, bb3 = 0.f;
    if (c < Fo) {
        bb0 = b1[c + 0] + b2[c + 0];
        bb1 = b1[c + 1] + b2[c + 1];
        bb2 = b1[c + 2] + b2[c + 2];
        bb3 = b1[c + 3] + b2[c + 3];
    }

    if (!doFinal) {
        if (c < Fo) {
#pragma unroll
            for (int i = 0; i < 8; ++i) {
                int r = row0 + ty * 8 + i;
                if (r < NN) {
                    float4 v;
                    v.x = acc[i][0] + bb0;
                    v.y = acc[i][1] + bb1;
                    v.z = acc[i][2] + bb2;
                    v.w = acc[i][3] + bb3;
                    if (doRelu) {
                        v.x = fmaxf(v.x, 0.f); v.y = fmaxf(v.y, 0.f);
                        v.z = fmaxf(v.z, 0.f); v.w = fmaxf(v.w, 0.f);
                    }
                    *(float4*)(out + (size_t)r * Fo + c) = v;
                }
            }
        }
    } else {
        // fused log-softmax: 16 lanes sharing ty hold one row's 64 padded cols
        // (40 valid). xor-shuffle 8,4,2,1 stays within the 16-lane group.
        bool valid = (c < Fo);
#pragma unroll
        for (int i = 0; i < 8; ++i) {
            int r = row0 + ty * 8 + i;
            float v0 = acc[i][0] + bb0;
            float v1 = acc[i][1] + bb1;
            float v2 = acc[i][2] + bb2;
            float v3 = acc[i][3] + bb3;
            float m = valid ? fmaxf(fmaxf(v0, v1), fmaxf(v2, v3)) : -FLT_MAX;
#pragma unroll
            for (int o = 8; o > 0; o >>= 1)
                m = fmaxf(m, __shfl_xor_sync(0xFFFFFFFFu, m, o));
            float s = valid ? (__expf(v0 - m) + __expf(v1 - m) +
                               __expf(v2 - m) + __expf(v3 - m)) : 0.f;
#pragma unroll
            for (int o = 8; o > 0; o >>= 1)
                s += __shfl_xor_sync(0xFFFFFFFFu, s, o);
            float ls = m + logf(s);
            if (valid && r < NN) {
                float4 v;
                v.x = v0 - ls; v.y = v1 - ls; v.z = v2 - ls; v.w = v3 - ls;
                *(float4*)(out + (size_t)r * Fo + c) = v;
            }
        }
    }
}

// ---------------- launch ----------------
extern "C" void kernel_launch(void* const* d_in, const int* in_sizes, int n_in,
                              void* d_out, int out_size) {
    const float* x   = (const float*)d_in[0];
    const int*   er  = (const int*)d_in[1];
    const int*   ec  = (const int*)d_in[2];
    const float* Wl0 = (const float*)d_in[5];
    const float* bl0 = (const float*)d_in[6];
    const float* Wr0 = (const float*)d_in[7];
    const float* br0 = (const float*)d_in[8];
    const float* Wl1 = (const float*)d_in[9];
    const float* bl1 = (const float*)d_in[10];
    const float* Wr1 = (const float*)d_in[11];
    const float* br1 = (const float*)d_in[12];
    const float* Wl2 = (const float*)d_in[13];
    const float* bl2 = (const float*)d_in[14];
    const float* Wr2 = (const float*)d_in[15];
    const float* br2 = (const float*)d_in[16];
    float* out = (float*)d_out;

    float* agg; cudaGetSymbolAddress((void**)&agg, g_agg);
    float* h1;  cudaGetSymbolAddress((void**)&h1,  g_h1);
    float* h2;  cudaGetSymbolAddress((void**)&h2,  g_h2);

    // preprocessing: zero counters + one-pass padded-ELL build
    k_zero_cnt<<<(NN + 1023) / 1024, 1024>>>();
    k_fill_ell<<<(EE + 255) / 256, 256>>>(er, ec);

    const int AGG_BLOCKS  = (NN + 7) / 8;        // warp per node, 8 warps per block
    const int GEMM_BLOCKS = (NN + 127) / 128;

    // layer 0   (launch idx: zero=2, fill=3, agg=4, gemm=5 <- ncu -s 5 captures gemm)
    k_agg<<<AGG_BLOCKS, 256>>>(x, agg);
    k_gemm<<<GEMM_BLOCKS, 256>>>(agg, x, Wl0, bl0, Wr0, br0, h1, FH, 1, 0);
    // layer 1
    k_agg<<<AGG_BLOCKS, 256>>>(h1, agg);
    k_gemm<<<GEMM_BLOCKS, 256>>>(agg, h1, Wl1, bl1, Wr1, br1, h2, FH, 1, 0);
    // layer 2: logits + fused log-softmax into d_out
    k_agg<<<AGG_BLOCKS, 256>>>(h2, agg);
    k_gemm<<<GEMM_BLOCKS, 256>>>(agg, h2, Wl2, bl2, Wr2, br2, out, FO, 0, 1);
}